// round 8
// baseline (speedup 1.0000x reference)
#include <cuda_runtime.h>
#include <cooperative_groups.h>
#include <math.h>
#include <stdint.h>

namespace cg = cooperative_groups;

// ---------------------------------------------------------------------------
// LogNCDE depth-2 log-ODE scan. 4-CTA cluster handles TWO batch elements,
// phases interleaved so barriers / cluster.syncs / reduce tails amortize 2x.
// Rank r owns channels {2r,2r+1} and Wv2 rows [128r,128r+128) (registers).
// f32x2 packed FMAs; fast activations; hoisted readout; a.V folded into the
// exchanged correction so V needs no double buffer.
// ---------------------------------------------------------------------------

namespace {
constexpr int kB   = 32;
constexpr int kT   = 2049;
constexpr int kD   = 8;
constexpr int kS   = 64;
constexpr int kH   = 128;
constexpr int kP   = 28;
constexpr int kNW  = 128;
constexpr int kWin = 16;
constexpr int kOut = 8;
constexpr int CL   = 4;
constexpr int NT   = 256;
constexpr int NB   = 2;      // batches per cluster

// shared-memory float offsets (all 16B aligned)
constexpr int OFF_SIGS  = 0;        // 2 x [128][36]
constexpr int OFF_CH    = 9216;     // 2 x [128][16]
constexpr int OFF_BV0   = 13312;    // 128
constexpr int OFF_BV1   = 13440;    // 128
constexpr int OFF_BV2S  = 13568;    // 128
constexpr int OFF_WR    = 13696;    // 512
constexpr int OFF_BR    = 14208;    // 8 (+pad)
constexpr int OFF_HH    = 14224;    // 2 x [129][64]
constexpr int OFF_Z0    = 30736;    // 2 x 128
constexpr int OFF_D0    = 30992;    // 2 x 128
constexpr int OFF_Z1    = 31248;    // 2 x 128
constexpr int OFF_D1    = 31504;    // 2 x 128
constexpr int OFF_V     = 31760;    // 2 x 512 (single buffer per batch)
constexpr int OFF_TDS   = 32784;    // 2 x 128
constexpr int OFF_WT    = 33040;    // 2 x 128
constexpr int OFF_PT    = 33296;    // 2 x 256
constexpr int OFF_UT    = 33808;    // 2 x 256
constexpr int OFF_RSLOT = 34320;    // 2 x 256
constexpr int OFF_PART  = 34832;    // 2 x 2048
constexpr int SMEMF     = 38928;    // ~156 KB
}  // namespace

static __device__ const int c_II[kP] =
    {0,0,0,0,0,0,0,1,1,1,1,1,1,2,2,2,2,2,3,3,3,3,4,4,4,5,5,6};
static __device__ const int c_JJ[kP] =
    {1,2,3,4,5,6,7,2,3,4,5,6,7,3,4,5,6,7,4,5,6,7,5,6,7,6,7,7};

using u64t = unsigned long long;

__device__ __forceinline__ int pidx(int i, int j) {   // Lyndon pair index, i<j
    return 7 * i - (i * (i - 1)) / 2 + (j - i - 1);
}
__device__ __forceinline__ u64t ffma2(u64t a, u64t b, u64t c) {
    u64t r;
    asm("fma.rn.f32x2 %0, %1, %2, %3;" : "=l"(r) : "l"(a), "l"(b), "l"(c));
    return r;
}
__device__ __forceinline__ float fold2(u64t a) {
    float lo, hi;
    asm("mov.b64 {%0, %1}, %2;" : "=f"(lo), "=f"(hi) : "l"(a));
    return lo + hi;
}
__device__ __forceinline__ float tanh_ap(float x) {
    float r; asm("tanh.approx.f32 %0, %1;" : "=f"(r) : "f"(x)); return r;
}
__device__ __forceinline__ void sp_sg(float s, float& z, float& d) {
    if (s > 20.f) { z = s; d = 1.f; }
    else {
        float e = __expf(s);
        float inv = __frcp_rn(1.f + e);
        z = __logf(1.f + e);
        d = e * inv;
    }
}
__device__ __forceinline__ float sp_f(float x) {   // accurate (one-time h0)
    return (x > 20.f) ? x : log1pf(expf(x));
}

__global__ __launch_bounds__(NT, 1) __cluster_dims__(CL, 1, 1)
void logncde_v8_kernel(
    const float* __restrict__ x,
    const float* __restrict__ Wi0, const float* __restrict__ bi0,
    const float* __restrict__ Wi1, const float* __restrict__ bi1,
    const float* __restrict__ Wi2, const float* __restrict__ bi2,
    const float* __restrict__ Wv0, const float* __restrict__ bv0,
    const float* __restrict__ Wv1, const float* __restrict__ bv1,
    const float* __restrict__ Wv2, const float* __restrict__ bv2,
    const float* __restrict__ Wr,  const float* __restrict__ br,
    float* __restrict__ out)
{
    extern __shared__ float sm[];
    cg::cluster_group cluster = cg::this_cluster();
    const int t    = threadIdx.x;
    const int rank = (int)cluster.block_rank();
    const int cid  = blockIdx.x >> 2;      // cluster id
    const int bg0  = 2 * cid;              // first batch of this cluster
    const int d0g  = 2 * rank;
    const int og   = t & 31;               // rows 4og..4og+3
    const int kg   = t >> 5;               // k-octant == warp id

    float* peer[CL - 1];
    #pragma unroll
    for (int p = 1; p < CL; p++)
        peer[p - 1] = cluster.map_shared_rank(sm, (rank + p) & (CL - 1));

    // ---- register weight tiles as packed f32x2 ----
    u64t w0p[16], w1p[32], w2p[32];
    {
        const ulonglong2* W0 = (const ulonglong2*)Wv0;   // [128][16]B-units
        #pragma unroll
        for (int r = 0; r < 4; r++)
            #pragma unroll
            for (int j = 0; j < 2; j++) {
                ulonglong2 v = W0[(4 * og + r) * 16 + kg * 2 + j];
                w0p[r * 4 + j * 2]     = v.x;
                w0p[r * 4 + j * 2 + 1] = v.y;
            }
        const ulonglong2* W1 = (const ulonglong2*)Wv1;   // [128][32]
        #pragma unroll
        for (int r = 0; r < 4; r++)
            #pragma unroll
            for (int j = 0; j < 4; j++) {
                ulonglong2 v = W1[(4 * og + r) * 32 + kg * 4 + j];
                w1p[r * 8 + j * 2]     = v.x;
                w1p[r * 8 + j * 2 + 1] = v.y;
            }
        const ulonglong2* W2 = (const ulonglong2*)Wv2;   // [512][32]
        #pragma unroll
        for (int r = 0; r < 4; r++)
            #pragma unroll
            for (int j = 0; j < 4; j++) {
                ulonglong2 v = W2[(kH * rank + 4 * og + r) * 32 + kg * 4 + j];
                w2p[r * 8 + j * 2]     = v.x;
                w2p[r * 8 + j * 2 + 1] = v.y;
            }
    }

    // ---- one-time staging ----
    for (int i = t; i < kH; i += NT) {
        sm[OFF_BV0 + i]  = bv0[i];
        sm[OFF_BV1 + i]  = bv1[i];
        sm[OFF_BV2S + i] = bv2[kH * rank + i];
    }
    for (int i = t; i < kOut * kS; i += NT) sm[OFF_WR + i] = Wr[i];
    if (t < kOut) sm[OFF_BR + t] = br[t];

    // ---- signatures: thread t -> batch (t>>7), window (t&127) ----
    {
        int bb = t >> 7, win = t & 127;
        const float* xb = x + (size_t)(bg0 + bb) * kT * kD + (size_t)win * kWin * kD;
        float cum[kD], prev[kD], Mm[kD * kD];
        #pragma unroll
        for (int i = 0; i < kD; i++) { cum[i] = 0.f; prev[i] = xb[i]; }
        #pragma unroll
        for (int i = 0; i < kD * kD; i++) Mm[i] = 0.f;
        for (int w = 0; w < kWin; w++) {
            float dl[kD];
            #pragma unroll
            for (int j = 0; j < kD; j++) {
                float cc = xb[(w + 1) * kD + j];
                dl[j] = cc - prev[j];
                prev[j] = cc;
            }
            #pragma unroll
            for (int i = 0; i < kD; i++)
                #pragma unroll
                for (int j = 0; j < kD; j++)
                    Mm[i * kD + j] = fmaf(cum[i], dl[j], Mm[i * kD + j]);
            #pragma unroll
            for (int i = 0; i < kD; i++) cum[i] += dl[i];
        }
        float* sgw = &sm[OFF_SIGS + bb * 4608 + win * 36];
        #pragma unroll
        for (int i = 0; i < kD; i++) sgw[i] = cum[i];
        #pragma unroll
        for (int p = 0; p < kP; p++) {
            int i = c_II[p], j = c_JJ[p];
            sgw[8 + p] = 0.5f * (Mm[i * kD + j] - Mm[j * kD + i]);
        }
    }
    __syncthreads();

    // ---- precompute C coefficients: 2 batches x 128 steps x 16 ----
    for (int i = t; i < 2 * kNW * 16; i += NT) {
        int bb = i >> 11, rem = i & 2047;
        int n = rem >> 4, j = rem & 15;
        int dl = j >> 3, e = j & 7;
        int d = d0g + dl;
        const float* sgn = &sm[OFF_SIGS + bb * 4608 + n * 36];
        float v = 0.f;
        if (e < d)      v =  sgn[8 + pidx(e, d)];
        else if (e > d) v = -sgn[8 + pidx(d, e)];
        sm[OFF_CH + bb * 2048 + n * 16 + dl * 8 + e] = v;
    }

    // ---- initial MLP h0 for both batches (accurate path) ----
    {
        int bb = t >> 7, o = t & 127;
        const float* x0 = x + (size_t)(bg0 + bb) * kT * kD;
        {
            float acc = bi0[o];
            #pragma unroll
            for (int k = 0; k < kD; k++) acc = fmaf(Wi0[o * kD + k], x0[k], acc);
            sm[OFF_Z0 + bb * kH + o] = sp_f(acc);
        }
        __syncthreads();
        {
            float acc = bi1[o];
            #pragma unroll 16
            for (int k = 0; k < kH; k++)
                acc = fmaf(Wi1[o * kH + k], sm[OFF_Z0 + bb * kH + k], acc);
            sm[OFF_Z1 + bb * kH + o] = sp_f(acc);
        }
        __syncthreads();
        if (o < kS) {
            float acc = bi2[o];
            #pragma unroll 16
            for (int k = 0; k < kH; k++)
                acc = fmaf(Wi2[o * kH + k], sm[OFF_Z1 + bb * kH + k], acc);
            sm[OFF_HH + bb * 8256 + o] = acc;
        }
        __syncthreads();
    }

    cluster.sync();

    float4* part4 = (float4*)&sm[OFF_PART];

    // ============================ scan loop ============================
    for (int n = 0; n < kNW; n++) {

        // --- A: z0-matvec for both batches
        #pragma unroll 1
        for (int bb = 0; bb < NB; bb++) {
            const ulonglong2* h2 =
                (const ulonglong2*)&sm[OFF_HH + bb * 8256 + n * kS];
            u64t a0 = 0, a1 = 0, a2 = 0, a3 = 0;
            #pragma unroll
            for (int j = 0; j < 2; j++) {
                ulonglong2 hv = h2[kg * 2 + j];
                a0 = ffma2(w0p[0 * 4 + j * 2], hv.x, a0);
                a0 = ffma2(w0p[0 * 4 + j * 2 + 1], hv.y, a0);
                a1 = ffma2(w0p[1 * 4 + j * 2], hv.x, a1);
                a1 = ffma2(w0p[1 * 4 + j * 2 + 1], hv.y, a1);
                a2 = ffma2(w0p[2 * 4 + j * 2], hv.x, a2);
                a2 = ffma2(w0p[2 * 4 + j * 2 + 1], hv.y, a2);
                a3 = ffma2(w0p[3 * 4 + j * 2], hv.x, a3);
                a3 = ffma2(w0p[3 * 4 + j * 2 + 1], hv.y, a3);
            }
            part4[bb * 512 + kg * 32 + og] =
                make_float4(fold2(a0), fold2(a1), fold2(a2), fold2(a3));
        }
        __syncthreads();
        {   // A-reduce: t<128 -> b0, t>=128 -> b1
            int bb = t >> 7, o = t & 127;
            int base = OFF_PART + bb * 2048;
            float s = sm[OFF_BV0 + o];
            #pragma unroll
            for (int q = 0; q < 8; q++) s += sm[base + q * kH + o];
            float z, d;
            sp_sg(s, z, d);
            sm[OFF_Z0 + bb * kH + o] = z;
            sm[OFF_D0 + bb * kH + o] = d;
        }
        __syncthreads();

        // --- B: z1-matvec
        #pragma unroll 1
        for (int bb = 0; bb < NB; bb++) {
            const ulonglong2* z2 = (const ulonglong2*)&sm[OFF_Z0 + bb * kH];
            u64t a0 = 0, a1 = 0, a2 = 0, a3 = 0;
            #pragma unroll
            for (int j = 0; j < 4; j++) {
                ulonglong2 zv = z2[kg * 4 + j];
                a0 = ffma2(w1p[0 * 8 + j * 2], zv.x, a0);
                a0 = ffma2(w1p[0 * 8 + j * 2 + 1], zv.y, a0);
                a1 = ffma2(w1p[1 * 8 + j * 2], zv.x, a1);
                a1 = ffma2(w1p[1 * 8 + j * 2 + 1], zv.y, a1);
                a2 = ffma2(w1p[2 * 8 + j * 2], zv.x, a2);
                a2 = ffma2(w1p[2 * 8 + j * 2 + 1], zv.y, a2);
                a3 = ffma2(w1p[3 * 8 + j * 2], zv.x, a3);
                a3 = ffma2(w1p[3 * 8 + j * 2 + 1], zv.y, a3);
            }
            part4[bb * 512 + kg * 32 + og] =
                make_float4(fold2(a0), fold2(a1), fold2(a2), fold2(a3));
        }
        __syncthreads();
        {
            int bb = t >> 7, o = t & 127;
            int base = OFF_PART + bb * 2048;
            float s = sm[OFF_BV1 + o];
            #pragma unroll
            for (int q = 0; q < 8; q++) s += sm[base + q * kH + o];
            float z, d;
            sp_sg(s, z, d);
            sm[OFF_Z1 + bb * kH + o] = z;
            sm[OFF_D1 + bb * kH + o] = d;
        }
        __syncthreads();

        // --- C: V-slice matvec
        #pragma unroll 1
        for (int bb = 0; bb < NB; bb++) {
            const ulonglong2* z2 = (const ulonglong2*)&sm[OFF_Z1 + bb * kH];
            u64t a0 = 0, a1 = 0, a2 = 0, a3 = 0;
            #pragma unroll
            for (int j = 0; j < 4; j++) {
                ulonglong2 zv = z2[kg * 4 + j];
                a0 = ffma2(w2p[0 * 8 + j * 2], zv.x, a0);
                a0 = ffma2(w2p[0 * 8 + j * 2 + 1], zv.y, a0);
                a1 = ffma2(w2p[1 * 8 + j * 2], zv.x, a1);
                a1 = ffma2(w2p[1 * 8 + j * 2 + 1], zv.y, a1);
                a2 = ffma2(w2p[2 * 8 + j * 2], zv.x, a2);
                a2 = ffma2(w2p[2 * 8 + j * 2 + 1], zv.y, a2);
                a3 = ffma2(w2p[3 * 8 + j * 2], zv.x, a3);
                a3 = ffma2(w2p[3 * 8 + j * 2 + 1], zv.y, a3);
            }
            part4[bb * 512 + kg * 32 + og] =
                make_float4(fold2(a0), fold2(a1), fold2(a2), fold2(a3));
        }
        __syncthreads();
        {   // C-reduce + V push (both batches, full CTA)
            int bb = t >> 7, o = t & 127;
            int base = OFF_PART + bb * 2048;
            float s = sm[OFF_BV2S + o];
            #pragma unroll
            for (int q = 0; q < 8; q++) s += sm[base + q * kH + o];
            float v = tanh_ap(s);
            int vi = OFF_V + bb * 512 + kH * rank + o;
            sm[vi] = v;
            sm[OFF_TDS + bb * kH + o] = 1.f - v * v;
            peer[0][vi] = v;
            peer[1][vi] = v;
            peer[2][vi] = v;
        }
        cluster.sync();   // V(n) for both batches gathered everywhere

        // --- D: tangents for both batches (full CTA)
        {
            int bb = t >> 7, dl = (t >> 6) & 1, a_ = t & 63;
            const float* cj = &sm[OFF_CH + bb * 2048 + n * 16 + dl * 8];
            const float* vv = &sm[OFF_V + bb * 512];
            float acc = 0.f;
            #pragma unroll
            for (int e = 0; e < kD; e++)
                acc = fmaf(cj[e], vv[e * kS + a_], acc);
            sm[OFF_WT + bb * kH + dl * kS + a_] = acc;
        }
        __syncthreads();

        // --- E: q = Wv0 wt (2 batches x 2 channels)
        #pragma unroll 1
        for (int bb = 0; bb < NB; bb++) {
            const ulonglong2* wt2 = (const ulonglong2*)&sm[OFF_WT + bb * kH];
            u64t a0 = 0, a1 = 0, a2 = 0, a3 = 0;
            u64t b0 = 0, b1 = 0, b2 = 0, b3 = 0;
            #pragma unroll
            for (int j = 0; j < 2; j++) {
                ulonglong2 v0 = wt2[kg * 2 + j];
                ulonglong2 v1 = wt2[16 + kg * 2 + j];
                a0 = ffma2(w0p[0 * 4 + j * 2], v0.x, a0);
                a0 = ffma2(w0p[0 * 4 + j * 2 + 1], v0.y, a0);
                a1 = ffma2(w0p[1 * 4 + j * 2], v0.x, a1);
                a1 = ffma2(w0p[1 * 4 + j * 2 + 1], v0.y, a1);
                a2 = ffma2(w0p[2 * 4 + j * 2], v0.x, a2);
                a2 = ffma2(w0p[2 * 4 + j * 2 + 1], v0.y, a2);
                a3 = ffma2(w0p[3 * 4 + j * 2], v0.x, a3);
                a3 = ffma2(w0p[3 * 4 + j * 2 + 1], v0.y, a3);
                b0 = ffma2(w0p[0 * 4 + j * 2], v1.x, b0);
                b0 = ffma2(w0p[0 * 4 + j * 2 + 1], v1.y, b0);
                b1 = ffma2(w0p[1 * 4 + j * 2], v1.x, b1);
                b1 = ffma2(w0p[1 * 4 + j * 2 + 1], v1.y, b1);
                b2 = ffma2(w0p[2 * 4 + j * 2], v1.x, b2);
                b2 = ffma2(w0p[2 * 4 + j * 2 + 1], v1.y, b2);
                b3 = ffma2(w0p[3 * 4 + j * 2], v1.x, b3);
                b3 = ffma2(w0p[3 * 4 + j * 2 + 1], v1.y, b3);
            }
            part4[bb * 512 + kg * 32 + og] =
                make_float4(fold2(a0), fold2(a1), fold2(a2), fold2(a3));
            part4[bb * 512 + 256 + kg * 32 + og] =
                make_float4(fold2(b0), fold2(b1), fold2(b2), fold2(b3));
        }
        __syncthreads();
        {   // pt = D0 .* q  (each thread: its batch, both channels)
            int bb = t >> 7, o = t & 127;
            int base = OFF_PART + bb * 2048;
            float d0v = sm[OFF_D0 + bb * kH + o];
            #pragma unroll
            for (int ch = 0; ch < 2; ch++) {
                float s = 0.f;
                #pragma unroll
                for (int q = 0; q < 8; q++)
                    s += sm[base + ch * 1024 + q * kH + o];
                sm[OFF_PT + bb * 256 + ch * kH + o] = s * d0v;
            }
        }
        __syncthreads();

        // --- F: u' = Wv1 pt (2 batches x 2 channels)
        #pragma unroll 1
        for (int bb = 0; bb < NB; bb++) {
            const ulonglong2* pt2 = (const ulonglong2*)&sm[OFF_PT + bb * 256];
            u64t a0 = 0, a1 = 0, a2 = 0, a3 = 0;
            u64t b0 = 0, b1 = 0, b2 = 0, b3 = 0;
            #pragma unroll
            for (int j = 0; j < 4; j++) {
                ulonglong2 v0 = pt2[kg * 4 + j];
                ulonglong2 v1 = pt2[32 + kg * 4 + j];
                a0 = ffma2(w1p[0 * 8 + j * 2], v0.x, a0);
                a0 = ffma2(w1p[0 * 8 + j * 2 + 1], v0.y, a0);
                a1 = ffma2(w1p[1 * 8 + j * 2], v0.x, a1);
                a1 = ffma2(w1p[1 * 8 + j * 2 + 1], v0.y, a1);
                a2 = ffma2(w1p[2 * 8 + j * 2], v0.x, a2);
                a2 = ffma2(w1p[2 * 8 + j * 2 + 1], v0.y, a2);
                a3 = ffma2(w1p[3 * 8 + j * 2], v0.x, a3);
                a3 = ffma2(w1p[3 * 8 + j * 2 + 1], v0.y, a3);
                b0 = ffma2(w1p[0 * 8 + j * 2], v1.x, b0);
                b0 = ffma2(w1p[0 * 8 + j * 2 + 1], v1.y, b0);
                b1 = ffma2(w1p[1 * 8 + j * 2], v1.x, b1);
                b1 = ffma2(w1p[1 * 8 + j * 2 + 1], v1.y, b1);
                b2 = ffma2(w1p[2 * 8 + j * 2], v1.x, b2);
                b2 = ffma2(w1p[2 * 8 + j * 2 + 1], v1.y, b2);
                b3 = ffma2(w1p[3 * 8 + j * 2], v1.x, b3);
                b3 = ffma2(w1p[3 * 8 + j * 2 + 1], v1.y, b3);
            }
            part4[bb * 512 + kg * 32 + og] =
                make_float4(fold2(a0), fold2(a1), fold2(a2), fold2(a3));
            part4[bb * 512 + 256 + kg * 32 + og] =
                make_float4(fold2(b0), fold2(b1), fold2(b2), fold2(b3));
        }
        __syncthreads();
        {   // ut = D1 .* u'
            int bb = t >> 7, o = t & 127;
            int base = OFF_PART + bb * 2048;
            float d1v = sm[OFF_D1 + bb * kH + o];
            #pragma unroll
            for (int ch = 0; ch < 2; ch++) {
                float s = 0.f;
                #pragma unroll
                for (int q = 0; q < 8; q++)
                    s += sm[base + ch * 1024 + q * kH + o];
                sm[OFF_UT + bb * 256 + ch * kH + o] = s * d1v;
            }
        }
        __syncthreads();

        // --- G: r = Wv2s ut_{channel(row)} (2 batches)
        #pragma unroll 1
        for (int bb = 0; bb < NB; bb++) {
            int dl = og >> 4;
            const ulonglong2* u2 =
                (const ulonglong2*)&sm[OFF_UT + bb * 256 + dl * kH];
            u64t a0 = 0, a1 = 0, a2 = 0, a3 = 0;
            #pragma unroll
            for (int j = 0; j < 4; j++) {
                ulonglong2 uv = u2[kg * 4 + j];
                a0 = ffma2(w2p[0 * 8 + j * 2], uv.x, a0);
                a0 = ffma2(w2p[0 * 8 + j * 2 + 1], uv.y, a0);
                a1 = ffma2(w2p[1 * 8 + j * 2], uv.x, a1);
                a1 = ffma2(w2p[1 * 8 + j * 2 + 1], uv.y, a1);
                a2 = ffma2(w2p[2 * 8 + j * 2], uv.x, a2);
                a2 = ffma2(w2p[2 * 8 + j * 2 + 1], uv.y, a2);
                a3 = ffma2(w2p[3 * 8 + j * 2], uv.x, a3);
                a3 = ffma2(w2p[3 * 8 + j * 2 + 1], uv.y, a3);
            }
            part4[bb * 512 + kg * 32 + og] =
                make_float4(fold2(a0), fold2(a1), fold2(a2), fold2(a3));
        }
        __syncthreads();
        // G-reduce: correction c = TD.*r folded + a.V(own) ; push to peers
        if (t < kH) {
            int bb = t >> 6, a_ = t & 63;
            int base = OFF_PART + bb * 2048;
            float s0 = 0.f, s1 = 0.f;
            #pragma unroll
            for (int q = 0; q < 8; q++) {
                s0 += sm[base + q * kH + a_];
                s1 += sm[base + q * kH + kS + a_];
            }
            const float* sgn = &sm[OFF_SIGS + bb * 4608 + n * 36];
            const float* vv  = &sm[OFF_V + bb * 512];
            float rs = s0 * sm[OFF_TDS + bb * kH + a_]
                     + s1 * sm[OFF_TDS + bb * kH + kS + a_]
                     + sgn[d0g]     * vv[d0g * kS + a_]
                     + sgn[d0g + 1] * vv[(d0g + 1) * kS + a_];
            int ri = OFF_RSLOT + bb * 256 + kS * rank + a_;
            sm[ri] = rs;
            peer[0][ri] = rs;
            peer[1][ri] = rs;
            peer[2][ri] = rs;
        }
        cluster.sync();   // corrections for both batches gathered

        // --- H: h_{n+1} = h_n + sum_p c_p (both batches)
        if (t < kH) {
            int bb = t >> 6, a_ = t & 63;
            float acc = sm[OFF_HH + bb * 8256 + n * kS + a_];
            #pragma unroll
            for (int p = 0; p < CL; p++)
                acc += sm[OFF_RSLOT + bb * 256 + p * kS + a_];
            sm[OFF_HH + bb * 8256 + (n + 1) * kS + a_] = acc;
        }
        __syncthreads();
    }

    // ---- readout of both batches' h history (rank 0) ----
    if (rank == 0) {
        for (int idx = t; idx < 2 * (kNW + 1) * kOut; idx += NT) {
            int bb = idx >= (kNW + 1) * kOut;
            int rem = idx - bb * (kNW + 1) * kOut;
            int n = rem >> 3, o = rem & 7;
            float acc = sm[OFF_BR + o];
            const float* hh = &sm[OFF_HH + bb * 8256 + n * kS];
            #pragma unroll 16
            for (int a = 0; a < kS; a++)
                acc = fmaf(sm[OFF_WR + o * kS + a], hh[a], acc);
            out[((size_t)(bg0 + bb) * (kNW + 1) + n) * kOut + o] = acc;
        }
    }
    cluster.sync();   // no CTA exits while peers may still touch its smem
}

extern "C" void kernel_launch(void* const* d_in, const int* in_sizes, int n_in,
                              void* d_out, int out_size) {
    // metadata order: ts, x, Wi0,bi0, Wi1,bi1, Wi2,bi2, Wv0,bv0, Wv1,bv1, Wv2,bv2, Wr,br
    const float* x   = (const float*)d_in[1];
    const float* Wi0 = (const float*)d_in[2];
    const float* bi0 = (const float*)d_in[3];
    const float* Wi1 = (const float*)d_in[4];
    const float* bi1 = (const float*)d_in[5];
    const float* Wi2 = (const float*)d_in[6];
    const float* bi2 = (const float*)d_in[7];
    const float* Wv0 = (const float*)d_in[8];
    const float* bv0 = (const float*)d_in[9];
    const float* Wv1 = (const float*)d_in[10];
    const float* bv1 = (const float*)d_in[11];
    const float* Wv2 = (const float*)d_in[12];
    const float* bv2 = (const float*)d_in[13];
    const float* Wr  = (const float*)d_in[14];
    const float* br  = (const float*)d_in[15];
    float* out = (float*)d_out;

    cudaFuncSetAttribute(logncde_v8_kernel,
                         cudaFuncAttributeMaxDynamicSharedMemorySize,
                         SMEMF * (int)sizeof(float));
    logncde_v8_kernel<<<(kB / NB) * CL, NT, SMEMF * sizeof(float)>>>(
        x, Wi0, bi0, Wi1, bi1, Wi2, bi2,
        Wv0, bv0, Wv1, bv1, Wv2, bv2, Wr, br, out);
}

// round 9
// speedup vs baseline: 1.0402x; 1.0402x over previous
#include <cuda_runtime.h>
#include <cooperative_groups.h>
#include <math.h>
#include <stdint.h>

namespace cg = cooperative_groups;

// ---------------------------------------------------------------------------
// LogNCDE depth-2 log-ODE scan. 4-CTA cluster handles TWO batch elements
// (barriers / cluster.syncs / reduce tails amortized 2x). Rank r owns
// channels {2r,2r+1} and Wv2 rows [128r,128r+128) in REGISTERS (f32x2 pairs).
// Signatures + h0 computed in a separate prep kernel so the scan kernel's
// register allocation is dominated by the weight tiles (no spills).
// ---------------------------------------------------------------------------

namespace {
constexpr int kB   = 32;
constexpr int kT   = 2049;
constexpr int kD   = 8;
constexpr int kS   = 64;
constexpr int kH   = 128;
constexpr int kP   = 28;
constexpr int kNW  = 128;
constexpr int kWin = 16;
constexpr int kOut = 8;
constexpr int CL   = 4;
constexpr int NT   = 256;
constexpr int NB   = 2;      // batches per cluster

// shared-memory float offsets (16B aligned)
constexpr int OFF_SIGS  = 0;        // 2 x [128][36]
constexpr int OFF_CH    = 9216;     // 2 x [128][16]
constexpr int OFF_BV0   = 13312;    // 128
constexpr int OFF_BV1   = 13440;    // 128
constexpr int OFF_BV2S  = 13568;    // 128
constexpr int OFF_WR    = 13696;    // 512
constexpr int OFF_BR    = 14208;    // 8 (+pad)
constexpr int OFF_HH    = 14224;    // 2 x [129][64]
constexpr int OFF_Z0    = 30736;    // 2 x 128
constexpr int OFF_D0    = 30992;    // 2 x 128
constexpr int OFF_Z1    = 31248;    // 2 x 128
constexpr int OFF_D1    = 31504;    // 2 x 128
constexpr int OFF_V     = 31760;    // 2 x 512
constexpr int OFF_TDS   = 32784;    // 2 x 128
constexpr int OFF_WT    = 33040;    // 2 x 128
constexpr int OFF_PT    = 33296;    // 2 x 256
constexpr int OFF_UT    = 33808;    // 2 x 256
constexpr int OFF_RSLOT = 34320;    // 2 x 256
constexpr int OFF_PART  = 34832;    // 2 x 2048
constexpr int SMEMF     = 38928;    // ~156 KB
}  // namespace

__device__ float g_sigs[kB * kNW * 36];   // per-batch window signatures
__device__ float g_h0[kB * kS];           // per-batch initial state

static __device__ const int c_II[kP] =
    {0,0,0,0,0,0,0,1,1,1,1,1,1,2,2,2,2,2,3,3,3,3,4,4,4,5,5,6};
static __device__ const int c_JJ[kP] =
    {1,2,3,4,5,6,7,2,3,4,5,6,7,3,4,5,6,7,4,5,6,7,5,6,7,6,7,7};

using u64t = unsigned long long;

__device__ __forceinline__ int pidx(int i, int j) {   // Lyndon pair index, i<j
    return 7 * i - (i * (i - 1)) / 2 + (j - i - 1);
}
__device__ __forceinline__ u64t ffma2(u64t a, u64t b, u64t c) {
    u64t r;
    asm("fma.rn.f32x2 %0, %1, %2, %3;" : "=l"(r) : "l"(a), "l"(b), "l"(c));
    return r;
}
__device__ __forceinline__ float fold2(u64t a) {
    float lo, hi;
    asm("mov.b64 {%0, %1}, %2;" : "=f"(lo), "=f"(hi) : "l"(a));
    return lo + hi;
}
__device__ __forceinline__ float tanh_ap(float x) {
    float r; asm("tanh.approx.f32 %0, %1;" : "=f"(r) : "f"(x)); return r;
}
__device__ __forceinline__ void sp_sg(float s, float& z, float& d) {
    if (s > 20.f) { z = s; d = 1.f; }
    else {
        float e = __expf(s);
        float inv = __frcp_rn(1.f + e);
        z = __logf(1.f + e);
        d = e * inv;
    }
}
__device__ __forceinline__ float sp_f(float x) {   // accurate (one-time h0)
    return (x > 20.f) ? x : log1pf(expf(x));
}

// ======================= prep kernel: signatures + h0 =======================
__global__ __launch_bounds__(128, 1)
void logncde_prep_kernel(
    const float* __restrict__ x,
    const float* __restrict__ Wi0, const float* __restrict__ bi0,
    const float* __restrict__ Wi1, const float* __restrict__ bi1,
    const float* __restrict__ Wi2, const float* __restrict__ bi2)
{
    __shared__ float z0[kH], z1[kH];
    const int b = blockIdx.x;
    const int t = threadIdx.x;

    // depth-2 log-signature, one window per thread
    {
        const float* xb = x + (size_t)b * kT * kD + (size_t)t * kWin * kD;
        float cum[kD], prev[kD], Mm[kD * kD];
        #pragma unroll
        for (int i = 0; i < kD; i++) { cum[i] = 0.f; prev[i] = xb[i]; }
        #pragma unroll
        for (int i = 0; i < kD * kD; i++) Mm[i] = 0.f;
        for (int w = 0; w < kWin; w++) {
            float dl[kD];
            #pragma unroll
            for (int j = 0; j < kD; j++) {
                float c = xb[(w + 1) * kD + j];
                dl[j] = c - prev[j];
                prev[j] = c;
            }
            #pragma unroll
            for (int i = 0; i < kD; i++)
                #pragma unroll
                for (int j = 0; j < kD; j++)
                    Mm[i * kD + j] = fmaf(cum[i], dl[j], Mm[i * kD + j]);
            #pragma unroll
            for (int i = 0; i < kD; i++) cum[i] += dl[i];
        }
        float* sgw = &g_sigs[((size_t)b * kNW + t) * 36];
        #pragma unroll
        for (int i = 0; i < kD; i++) sgw[i] = cum[i];
        #pragma unroll
        for (int p = 0; p < kP; p++) {
            int i = c_II[p], j = c_JJ[p];
            sgw[8 + p] = 0.5f * (Mm[i * kD + j] - Mm[j * kD + i]);
        }
    }

    // initial MLP h0 (accurate path)
    const float* x0 = x + (size_t)b * kT * kD;
    {
        float acc = bi0[t];
        #pragma unroll
        for (int k = 0; k < kD; k++) acc = fmaf(Wi0[t * kD + k], x0[k], acc);
        z0[t] = sp_f(acc);
    }
    __syncthreads();
    {
        float acc = bi1[t];
        #pragma unroll 16
        for (int k = 0; k < kH; k++) acc = fmaf(Wi1[t * kH + k], z0[k], acc);
        z1[t] = sp_f(acc);
    }
    __syncthreads();
    if (t < kS) {
        float acc = bi2[t];
        #pragma unroll 16
        for (int k = 0; k < kH; k++) acc = fmaf(Wi2[t * kH + k], z1[k], acc);
        g_h0[b * kS + t] = acc;
    }
}

// ============================== scan kernel ================================
__global__ __launch_bounds__(NT, 1) __cluster_dims__(CL, 1, 1)
void logncde_v9_kernel(
    const float* __restrict__ Wv0, const float* __restrict__ bv0,
    const float* __restrict__ Wv1, const float* __restrict__ bv1,
    const float* __restrict__ Wv2, const float* __restrict__ bv2,
    const float* __restrict__ Wr,  const float* __restrict__ br,
    float* __restrict__ out)
{
    extern __shared__ float sm[];
    cg::cluster_group cluster = cg::this_cluster();
    const int t    = threadIdx.x;
    const int rank = (int)cluster.block_rank();
    const int cid  = blockIdx.x >> 2;
    const int bg0  = 2 * cid;
    const int d0g  = 2 * rank;
    const int og   = t & 31;     // rows 4og..4og+3
    const int kg   = t >> 5;     // k-octant == warp id

    float* peer[CL - 1];
    #pragma unroll
    for (int p = 1; p < CL; p++)
        peer[p - 1] = cluster.map_shared_rank(sm, (rank + p) & (CL - 1));

    // ---- register weight tiles as packed f32x2 ----
    u64t w0p[16], w1p[32], w2p[32];
    {
        const ulonglong2* W0 = (const ulonglong2*)Wv0;   // [128][16] 16B units
        #pragma unroll
        for (int r = 0; r < 4; r++)
            #pragma unroll
            for (int j = 0; j < 2; j++) {
                ulonglong2 v = W0[(4 * og + r) * 16 + kg * 2 + j];
                w0p[r * 4 + j * 2]     = v.x;
                w0p[r * 4 + j * 2 + 1] = v.y;
            }
        const ulonglong2* W1 = (const ulonglong2*)Wv1;   // [128][32]
        #pragma unroll
        for (int r = 0; r < 4; r++)
            #pragma unroll
            for (int j = 0; j < 4; j++) {
                ulonglong2 v = W1[(4 * og + r) * 32 + kg * 4 + j];
                w1p[r * 8 + j * 2]     = v.x;
                w1p[r * 8 + j * 2 + 1] = v.y;
            }
        const ulonglong2* W2 = (const ulonglong2*)Wv2;   // [512][32]
        #pragma unroll
        for (int r = 0; r < 4; r++)
            #pragma unroll
            for (int j = 0; j < 4; j++) {
                ulonglong2 v = W2[(kH * rank + 4 * og + r) * 32 + kg * 4 + j];
                w2p[r * 8 + j * 2]     = v.x;
                w2p[r * 8 + j * 2 + 1] = v.y;
            }
    }

    // ---- staging: biases, readout, sigs (from prep), h0 (from prep) ----
    for (int i = t; i < kH; i += NT) {
        sm[OFF_BV0 + i]  = bv0[i];
        sm[OFF_BV1 + i]  = bv1[i];
        sm[OFF_BV2S + i] = bv2[kH * rank + i];
    }
    for (int i = t; i < kOut * kS; i += NT) sm[OFF_WR + i] = Wr[i];
    if (t < kOut) sm[OFF_BR + t] = br[t];

    {   // sigs for both batches: contiguous 9216 floats
        const float* src = &g_sigs[(size_t)bg0 * kNW * 36];
        for (int i = t; i < NB * kNW * 36; i += NT)
            sm[OFF_SIGS + i] = src[i];
    }
    for (int i = t; i < NB * kS; i += NT) {
        int bb = i >> 6;
        sm[OFF_HH + bb * 8256 + (i & 63)] = g_h0[bg0 * kS + i];
    }
    __syncthreads();

    // ---- precompute C coefficients: 2 batches x 128 steps x 16 ----
    for (int i = t; i < NB * kNW * 16; i += NT) {
        int bb = i >> 11, rem = i & 2047;
        int n = rem >> 4, j = rem & 15;
        int dl = j >> 3, e = j & 7;
        int d = d0g + dl;
        const float* sgn = &sm[OFF_SIGS + bb * 4608 + n * 36];
        float v = 0.f;
        if (e < d)      v =  sgn[8 + pidx(e, d)];
        else if (e > d) v = -sgn[8 + pidx(d, e)];
        sm[OFF_CH + bb * 2048 + n * 16 + dl * 8 + e] = v;
    }

    cluster.sync();

    float4* part4 = (float4*)&sm[OFF_PART];

    // ============================ scan loop ============================
    for (int n = 0; n < kNW; n++) {

        // --- A: z0-matvec for both batches
        #pragma unroll 1
        for (int bb = 0; bb < NB; bb++) {
            const ulonglong2* h2 =
                (const ulonglong2*)&sm[OFF_HH + bb * 8256 + n * kS];
            u64t a0 = 0, a1 = 0, a2 = 0, a3 = 0;
            #pragma unroll
            for (int j = 0; j < 2; j++) {
                ulonglong2 hv = h2[kg * 2 + j];
                a0 = ffma2(w0p[0 * 4 + j * 2], hv.x, a0);
                a0 = ffma2(w0p[0 * 4 + j * 2 + 1], hv.y, a0);
                a1 = ffma2(w0p[1 * 4 + j * 2], hv.x, a1);
                a1 = ffma2(w0p[1 * 4 + j * 2 + 1], hv.y, a1);
                a2 = ffma2(w0p[2 * 4 + j * 2], hv.x, a2);
                a2 = ffma2(w0p[2 * 4 + j * 2 + 1], hv.y, a2);
                a3 = ffma2(w0p[3 * 4 + j * 2], hv.x, a3);
                a3 = ffma2(w0p[3 * 4 + j * 2 + 1], hv.y, a3);
            }
            part4[bb * 512 + kg * 32 + og] =
                make_float4(fold2(a0), fold2(a1), fold2(a2), fold2(a3));
        }
        __syncthreads();
        {   // A-reduce: t<128 -> b0, t>=128 -> b1
            int bb = t >> 7, o = t & 127;
            int base = OFF_PART + bb * 2048;
            float s = sm[OFF_BV0 + o];
            #pragma unroll
            for (int q = 0; q < 8; q++) s += sm[base + q * kH + o];
            float z, d;
            sp_sg(s, z, d);
            sm[OFF_Z0 + bb * kH + o] = z;
            sm[OFF_D0 + bb * kH + o] = d;
        }
        __syncthreads();

        // --- B: z1-matvec
        #pragma unroll 1
        for (int bb = 0; bb < NB; bb++) {
            const ulonglong2* z2 = (const ulonglong2*)&sm[OFF_Z0 + bb * kH];
            u64t a0 = 0, a1 = 0, a2 = 0, a3 = 0;
            #pragma unroll
            for (int j = 0; j < 4; j++) {
                ulonglong2 zv = z2[kg * 4 + j];
                a0 = ffma2(w1p[0 * 8 + j * 2], zv.x, a0);
                a0 = ffma2(w1p[0 * 8 + j * 2 + 1], zv.y, a0);
                a1 = ffma2(w1p[1 * 8 + j * 2], zv.x, a1);
                a1 = ffma2(w1p[1 * 8 + j * 2 + 1], zv.y, a1);
                a2 = ffma2(w1p[2 * 8 + j * 2], zv.x, a2);
                a2 = ffma2(w1p[2 * 8 + j * 2 + 1], zv.y, a2);
                a3 = ffma2(w1p[3 * 8 + j * 2], zv.x, a3);
                a3 = ffma2(w1p[3 * 8 + j * 2 + 1], zv.y, a3);
            }
            part4[bb * 512 + kg * 32 + og] =
                make_float4(fold2(a0), fold2(a1), fold2(a2), fold2(a3));
        }
        __syncthreads();
        {
            int bb = t >> 7, o = t & 127;
            int base = OFF_PART + bb * 2048;
            float s = sm[OFF_BV1 + o];
            #pragma unroll
            for (int q = 0; q < 8; q++) s += sm[base + q * kH + o];
            float z, d;
            sp_sg(s, z, d);
            sm[OFF_Z1 + bb * kH + o] = z;
            sm[OFF_D1 + bb * kH + o] = d;
        }
        __syncthreads();

        // --- C: V-slice matvec
        #pragma unroll 1
        for (int bb = 0; bb < NB; bb++) {
            const ulonglong2* z2 = (const ulonglong2*)&sm[OFF_Z1 + bb * kH];
            u64t a0 = 0, a1 = 0, a2 = 0, a3 = 0;
            #pragma unroll
            for (int j = 0; j < 4; j++) {
                ulonglong2 zv = z2[kg * 4 + j];
                a0 = ffma2(w2p[0 * 8 + j * 2], zv.x, a0);
                a0 = ffma2(w2p[0 * 8 + j * 2 + 1], zv.y, a0);
                a1 = ffma2(w2p[1 * 8 + j * 2], zv.x, a1);
                a1 = ffma2(w2p[1 * 8 + j * 2 + 1], zv.y, a1);
                a2 = ffma2(w2p[2 * 8 + j * 2], zv.x, a2);
                a2 = ffma2(w2p[2 * 8 + j * 2 + 1], zv.y, a2);
                a3 = ffma2(w2p[3 * 8 + j * 2], zv.x, a3);
                a3 = ffma2(w2p[3 * 8 + j * 2 + 1], zv.y, a3);
            }
            part4[bb * 512 + kg * 32 + og] =
                make_float4(fold2(a0), fold2(a1), fold2(a2), fold2(a3));
        }
        __syncthreads();
        {   // C-reduce + V push (both batches, full CTA)
            int bb = t >> 7, o = t & 127;
            int base = OFF_PART + bb * 2048;
            float s = sm[OFF_BV2S + o];
            #pragma unroll
            for (int q = 0; q < 8; q++) s += sm[base + q * kH + o];
            float v = tanh_ap(s);
            int vi = OFF_V + bb * 512 + kH * rank + o;
            sm[vi] = v;
            sm[OFF_TDS + bb * kH + o] = 1.f - v * v;
            peer[0][vi] = v;
            peer[1][vi] = v;
            peer[2][vi] = v;
        }
        cluster.sync();   // V(n) for both batches gathered everywhere

        // --- D: tangents for both batches (full CTA)
        {
            int bb = t >> 7, dl = (t >> 6) & 1, a_ = t & 63;
            const float* cj = &sm[OFF_CH + bb * 2048 + n * 16 + dl * 8];
            const float* vv = &sm[OFF_V + bb * 512];
            float acc = 0.f;
            #pragma unroll
            for (int e = 0; e < kD; e++)
                acc = fmaf(cj[e], vv[e * kS + a_], acc);
            sm[OFF_WT + bb * kH + dl * kS + a_] = acc;
        }
        __syncthreads();

        // --- E: q = Wv0 wt (2 batches x 2 channels)
        #pragma unroll 1
        for (int bb = 0; bb < NB; bb++) {
            const ulonglong2* wt2 = (const ulonglong2*)&sm[OFF_WT + bb * kH];
            u64t a0 = 0, a1 = 0, a2 = 0, a3 = 0;
            u64t b0 = 0, b1 = 0, b2 = 0, b3 = 0;
            #pragma unroll
            for (int j = 0; j < 2; j++) {
                ulonglong2 v0 = wt2[kg * 2 + j];
                ulonglong2 v1 = wt2[16 + kg * 2 + j];
                a0 = ffma2(w0p[0 * 4 + j * 2], v0.x, a0);
                a0 = ffma2(w0p[0 * 4 + j * 2 + 1], v0.y, a0);
                a1 = ffma2(w0p[1 * 4 + j * 2], v0.x, a1);
                a1 = ffma2(w0p[1 * 4 + j * 2 + 1], v0.y, a1);
                a2 = ffma2(w0p[2 * 4 + j * 2], v0.x, a2);
                a2 = ffma2(w0p[2 * 4 + j * 2 + 1], v0.y, a2);
                a3 = ffma2(w0p[3 * 4 + j * 2], v0.x, a3);
                a3 = ffma2(w0p[3 * 4 + j * 2 + 1], v0.y, a3);
                b0 = ffma2(w0p[0 * 4 + j * 2], v1.x, b0);
                b0 = ffma2(w0p[0 * 4 + j * 2 + 1], v1.y, b0);
                b1 = ffma2(w0p[1 * 4 + j * 2], v1.x, b1);
                b1 = ffma2(w0p[1 * 4 + j * 2 + 1], v1.y, b1);
                b2 = ffma2(w0p[2 * 4 + j * 2], v1.x, b2);
                b2 = ffma2(w0p[2 * 4 + j * 2 + 1], v1.y, b2);
                b3 = ffma2(w0p[3 * 4 + j * 2], v1.x, b3);
                b3 = ffma2(w0p[3 * 4 + j * 2 + 1], v1.y, b3);
            }
            part4[bb * 512 + kg * 32 + og] =
                make_float4(fold2(a0), fold2(a1), fold2(a2), fold2(a3));
            part4[bb * 512 + 256 + kg * 32 + og] =
                make_float4(fold2(b0), fold2(b1), fold2(b2), fold2(b3));
        }
        __syncthreads();
        {   // pt = D0 .* q  (each thread: its batch, both channels)
            int bb = t >> 7, o = t & 127;
            int base = OFF_PART + bb * 2048;
            float d0v = sm[OFF_D0 + bb * kH + o];
            #pragma unroll
            for (int ch = 0; ch < 2; ch++) {
                float s = 0.f;
                #pragma unroll
                for (int q = 0; q < 8; q++)
                    s += sm[base + ch * 1024 + q * kH + o];
                sm[OFF_PT + bb * 256 + ch * kH + o] = s * d0v;
            }
        }
        __syncthreads();

        // --- F: u' = Wv1 pt (2 batches x 2 channels)
        #pragma unroll 1
        for (int bb = 0; bb < NB; bb++) {
            const ulonglong2* pt2 = (const ulonglong2*)&sm[OFF_PT + bb * 256];
            u64t a0 = 0, a1 = 0, a2 = 0, a3 = 0;
            u64t b0 = 0, b1 = 0, b2 = 0, b3 = 0;
            #pragma unroll
            for (int j = 0; j < 4; j++) {
                ulonglong2 v0 = pt2[kg * 4 + j];
                ulonglong2 v1 = pt2[32 + kg * 4 + j];
                a0 = ffma2(w1p[0 * 8 + j * 2], v0.x, a0);
                a0 = ffma2(w1p[0 * 8 + j * 2 + 1], v0.y, a0);
                a1 = ffma2(w1p[1 * 8 + j * 2], v0.x, a1);
                a1 = ffma2(w1p[1 * 8 + j * 2 + 1], v0.y, a1);
                a2 = ffma2(w1p[2 * 8 + j * 2], v0.x, a2);
                a2 = ffma2(w1p[2 * 8 + j * 2 + 1], v0.y, a2);
                a3 = ffma2(w1p[3 * 8 + j * 2], v0.x, a3);
                a3 = ffma2(w1p[3 * 8 + j * 2 + 1], v0.y, a3);
                b0 = ffma2(w1p[0 * 8 + j * 2], v1.x, b0);
                b0 = ffma2(w1p[0 * 8 + j * 2 + 1], v1.y, b0);
                b1 = ffma2(w1p[1 * 8 + j * 2], v1.x, b1);
                b1 = ffma2(w1p[1 * 8 + j * 2 + 1], v1.y, b1);
                b2 = ffma2(w1p[2 * 8 + j * 2], v1.x, b2);
                b2 = ffma2(w1p[2 * 8 + j * 2 + 1], v1.y, b2);
                b3 = ffma2(w1p[3 * 8 + j * 2], v1.x, b3);
                b3 = ffma2(w1p[3 * 8 + j * 2 + 1], v1.y, b3);
            }
            part4[bb * 512 + kg * 32 + og] =
                make_float4(fold2(a0), fold2(a1), fold2(a2), fold2(a3));
            part4[bb * 512 + 256 + kg * 32 + og] =
                make_float4(fold2(b0), fold2(b1), fold2(b2), fold2(b3));
        }
        __syncthreads();
        {   // ut = D1 .* u'
            int bb = t >> 7, o = t & 127;
            int base = OFF_PART + bb * 2048;
            float d1v = sm[OFF_D1 + bb * kH + o];
            #pragma unroll
            for (int ch = 0; ch < 2; ch++) {
                float s = 0.f;
                #pragma unroll
                for (int q = 0; q < 8; q++)
                    s += sm[base + ch * 1024 + q * kH + o];
                sm[OFF_UT + bb * 256 + ch * kH + o] = s * d1v;
            }
        }
        __syncthreads();

        // --- G: r = Wv2s ut_{channel(row)} (2 batches)
        #pragma unroll 1
        for (int bb = 0; bb < NB; bb++) {
            int dl = og >> 4;
            const ulonglong2* u2 =
                (const ulonglong2*)&sm[OFF_UT + bb * 256 + dl * kH];
            u64t a0 = 0, a1 = 0, a2 = 0, a3 = 0;
            #pragma unroll
            for (int j = 0; j < 4; j++) {
                ulonglong2 uv = u2[kg * 4 + j];
                a0 = ffma2(w2p[0 * 8 + j * 2], uv.x, a0);
                a0 = ffma2(w2p[0 * 8 + j * 2 + 1], uv.y, a0);
                a1 = ffma2(w2p[1 * 8 + j * 2], uv.x, a1);
                a1 = ffma2(w2p[1 * 8 + j * 2 + 1], uv.y, a1);
                a2 = ffma2(w2p[2 * 8 + j * 2], uv.x, a2);
                a2 = ffma2(w2p[2 * 8 + j * 2 + 1], uv.y, a2);
                a3 = ffma2(w2p[3 * 8 + j * 2], uv.x, a3);
                a3 = ffma2(w2p[3 * 8 + j * 2 + 1], uv.y, a3);
            }
            part4[bb * 512 + kg * 32 + og] =
                make_float4(fold2(a0), fold2(a1), fold2(a2), fold2(a3));
        }
        __syncthreads();
        // G-reduce: correction c = TD.*r folded + a.V(own) ; push to peers
        if (t < kH) {
            int bb = t >> 6, a_ = t & 63;
            int base = OFF_PART + bb * 2048;
            float s0 = 0.f, s1 = 0.f;
            #pragma unroll
            for (int q = 0; q < 8; q++) {
                s0 += sm[base + q * kH + a_];
                s1 += sm[base + q * kH + kS + a_];
            }
            const float* sgn = &sm[OFF_SIGS + bb * 4608 + n * 36];
            const float* vv  = &sm[OFF_V + bb * 512];
            float rs = s0 * sm[OFF_TDS + bb * kH + a_]
                     + s1 * sm[OFF_TDS + bb * kH + kS + a_]
                     + sgn[d0g]     * vv[d0g * kS + a_]
                     + sgn[d0g + 1] * vv[(d0g + 1) * kS + a_];
            int ri = OFF_RSLOT + bb * 256 + kS * rank + a_;
            sm[ri] = rs;
            peer[0][ri] = rs;
            peer[1][ri] = rs;
            peer[2][ri] = rs;
        }
        cluster.sync();   // corrections for both batches gathered

        // --- H: h_{n+1} = h_n + sum_p c_p (both batches)
        if (t < kH) {
            int bb = t >> 6, a_ = t & 63;
            float acc = sm[OFF_HH + bb * 8256 + n * kS + a_];
            #pragma unroll
            for (int p = 0; p < CL; p++)
                acc += sm[OFF_RSLOT + bb * 256 + p * kS + a_];
            sm[OFF_HH + bb * 8256 + (n + 1) * kS + a_] = acc;
        }
        __syncthreads();
    }

    // ---- readout of both batches' h history (rank 0) ----
    if (rank == 0) {
        for (int idx = t; idx < NB * (kNW + 1) * kOut; idx += NT) {
            int bb = idx >= (kNW + 1) * kOut;
            int rem = idx - bb * (kNW + 1) * kOut;
            int n = rem >> 3, o = rem & 7;
            float acc = sm[OFF_BR + o];
            const float* hh = &sm[OFF_HH + bb * 8256 + n * kS];
            #pragma unroll 16
            for (int a = 0; a < kS; a++)
                acc = fmaf(sm[OFF_WR + o * kS + a], hh[a], acc);
            out[((size_t)(bg0 + bb) * (kNW + 1) + n) * kOut + o] = acc;
        }
    }
    cluster.sync();   // no CTA exits while peers may still touch its smem
}

extern "C" void kernel_launch(void* const* d_in, const int* in_sizes, int n_in,
                              void* d_out, int out_size) {
    // metadata order: ts, x, Wi0,bi0, Wi1,bi1, Wi2,bi2, Wv0,bv0, Wv1,bv1, Wv2,bv2, Wr,br
    const float* x   = (const float*)d_in[1];
    const float* Wi0 = (const float*)d_in[2];
    const float* bi0 = (const float*)d_in[3];
    const float* Wi1 = (const float*)d_in[4];
    const float* bi1 = (const float*)d_in[5];
    const float* Wi2 = (const float*)d_in[6];
    const float* bi2 = (const float*)d_in[7];
    const float* Wv0 = (const float*)d_in[8];
    const float* bv0 = (const float*)d_in[9];
    const float* Wv1 = (const float*)d_in[10];
    const float* bv1 = (const float*)d_in[11];
    const float* Wv2 = (const float*)d_in[12];
    const float* bv2 = (const float*)d_in[13];
    const float* Wr  = (const float*)d_in[14];
    const float* br  = (const float*)d_in[15];
    float* out = (float*)d_out;

    logncde_prep_kernel<<<kB, 128>>>(x, Wi0, bi0, Wi1, bi1, Wi2, bi2);

    cudaFuncSetAttribute(logncde_v9_kernel,
                         cudaFuncAttributeMaxDynamicSharedMemorySize,
                         SMEMF * (int)sizeof(float));
    logncde_v9_kernel<<<(kB / NB) * CL, NT, SMEMF * sizeof(float)>>>(
        Wv0, bv0, Wv1, bv1, Wv2, bv2, Wr, br, out);
}